// round 6
// baseline (speedup 1.0000x reference)
#include <cuda_runtime.h>
#include <math.h>
#include <stdint.h>

// Problem constants
#define BB 8
#define TT 448
#define SS 1500
#define DD 1024
#define HH 16
#define DH 64
#define OUT_ELEMS (BB*TT*DD)

// Scratch
__device__ float g_q [BB*TT*DD];
__device__ float g_k [BB*SS*DD];
__device__ float g_v [BB*SS*DD];
__device__ float g_wv[BB*TT*DD];

// ---------------------------------------------------------------------------
// tf32 helpers
// ---------------------------------------------------------------------------
__device__ __forceinline__ uint32_t f2tf32(float f) {
    uint32_t r;
    asm("cvt.rna.tf32.f32 %0, %1;" : "=r"(r) : "f"(f));
    return r;
}
__device__ __forceinline__ float4 cvt4(float4 v) {
    return make_float4(__uint_as_float(f2tf32(v.x)), __uint_as_float(f2tf32(v.y)),
                       __uint_as_float(f2tf32(v.z)), __uint_as_float(f2tf32(v.w)));
}
// D(16x8,f32) += A(16x8,tf32,row) * B(8x8,tf32,col)
__device__ __forceinline__ void mma8(float* c, const uint32_t* a, const uint32_t* b) {
    asm volatile("mma.sync.aligned.m16n8k8.row.col.f32.tf32.tf32.f32 "
        "{%0,%1,%2,%3}, {%4,%5,%6,%7}, {%8,%9}, {%0,%1,%2,%3};"
        : "+f"(c[0]), "+f"(c[1]), "+f"(c[2]), "+f"(c[3])
        : "r"(a[0]), "r"(a[1]), "r"(a[2]), "r"(a[3]), "r"(b[0]), "r"(b[1]));
}

// ---------------------------------------------------------------------------
// tf32 GEMM v3: C = (A@B + bias) * alpha
// 128x128 block tile, BK=16 double-buffered, 128 threads (4 warps 2x2),
// warp tile 64x64.
// ---------------------------------------------------------------------------
#define GASTR 20
#define GBSTR 136

__global__ __launch_bounds__(128, 2) void gemm_tf32(
    const float* __restrict__ A, const float* __restrict__ Bm,
    const float* __restrict__ bias, float* __restrict__ C,
    int M, int N, int K, float alpha)
{
    __shared__ float As[2][128 * GASTR];   // [m][k]
    __shared__ float Bs[2][16  * GBSTR];   // [k][n]

    const int tid  = threadIdx.x;
    const int warp = tid >> 5, lane = tid & 31;
    const int wm = warp >> 1, wn = warp & 1;   // 2x2 warp grid, 64x64 tiles
    const int g  = lane >> 2, tg = lane & 3;
    const int m0 = blockIdx.y * 128, n0 = blockIdx.x * 128;

    const int ar0 = tid >> 2, ac0 = (tid & 3) << 2;   // A rows ar0+32i, cols ac0
    const int br0 = tid >> 5, bc0 = lane << 2;        // B rows br0+4i, cols bc0

    float acc[4][8][4];
#pragma unroll
    for (int mi = 0; mi < 4; mi++)
#pragma unroll
        for (int nj = 0; nj < 8; nj++)
#pragma unroll
            for (int r = 0; r < 4; r++) acc[mi][nj][r] = 0.f;

    const int nt = K >> 4;

    // prologue: tile 0 -> stage 0
#pragma unroll
    for (int i = 0; i < 4; i++) {
        int ra = ar0 + i * 32;
        float4 av = make_float4(0,0,0,0);
        if (m0 + ra < M) av = *(const float4*)(A + (size_t)(m0 + ra) * K + ac0);
        *(float4*)(As[0] + ra * GASTR + ac0) = cvt4(av);
        int rb = br0 + i * 4;
        float4 bvv = *(const float4*)(Bm + (size_t)rb * N + n0 + bc0);
        *(float4*)(Bs[0] + rb * GBSTR + bc0) = cvt4(bvv);
    }
    __syncthreads();

    for (int t = 0; t < nt; t++) {
        const int cur = t & 1;
        float4 pa[4], pb[4];
        const bool more = (t + 1 < nt);
        if (more) {
            const int k0 = (t + 1) << 4;
#pragma unroll
            for (int i = 0; i < 4; i++) {
                int ra = ar0 + i * 32;
                pa[i] = make_float4(0,0,0,0);
                if (m0 + ra < M)
                    pa[i] = *(const float4*)(A + (size_t)(m0 + ra) * K + k0 + ac0);
                pb[i] = *(const float4*)(Bm + (size_t)(k0 + br0 + i * 4) * N + n0 + bc0);
            }
        }

#pragma unroll
        for (int kk = 0; kk < 16; kk += 8) {
            uint32_t af[4][4], bf[8][2];
#pragma unroll
            for (int mi = 0; mi < 4; mi++) {
                int row = wm * 64 + mi * 16 + g;
                af[mi][0] = __float_as_uint(As[cur][row * GASTR + kk + tg]);
                af[mi][1] = __float_as_uint(As[cur][(row + 8) * GASTR + kk + tg]);
                af[mi][2] = __float_as_uint(As[cur][row * GASTR + kk + tg + 4]);
                af[mi][3] = __float_as_uint(As[cur][(row + 8) * GASTR + kk + tg + 4]);
            }
#pragma unroll
            for (int nj = 0; nj < 8; nj++) {
                int col = wn * 64 + nj * 8 + g;
                bf[nj][0] = __float_as_uint(Bs[cur][(kk + tg) * GBSTR + col]);
                bf[nj][1] = __float_as_uint(Bs[cur][(kk + tg + 4) * GBSTR + col]);
            }
#pragma unroll
            for (int mi = 0; mi < 4; mi++)
#pragma unroll
                for (int nj = 0; nj < 8; nj++)
                    mma8(acc[mi][nj], af[mi], bf[nj]);
        }

        if (more) {
            const int nxt = cur ^ 1;
#pragma unroll
            for (int i = 0; i < 4; i++) {
                *(float4*)(As[nxt] + (ar0 + i * 32) * GASTR + ac0) = cvt4(pa[i]);
                *(float4*)(Bs[nxt] + (br0 + i * 4) * GBSTR + bc0)  = cvt4(pb[i]);
            }
        }
        __syncthreads();
    }

    // Epilogue
#pragma unroll
    for (int nj = 0; nj < 8; nj++) {
        int col = n0 + wn * 64 + nj * 8 + tg * 2;
        float2 bv = make_float2(0.f, 0.f);
        if (bias) bv = *(const float2*)(bias + col);
#pragma unroll
        for (int mi = 0; mi < 4; mi++) {
            int r0 = m0 + wm * 64 + mi * 16 + g;
            if (r0 < M) {
                float2 o = make_float2((acc[mi][nj][0] + bv.x) * alpha,
                                       (acc[mi][nj][1] + bv.y) * alpha);
                *(float2*)(C + (size_t)r0 * N + col) = o;
            }
            if (r0 + 8 < M) {
                float2 o = make_float2((acc[mi][nj][2] + bv.x) * alpha,
                                       (acc[mi][nj][3] + bv.y) * alpha);
                *(float2*)(C + (size_t)(r0 + 8) * N + col) = o;
            }
        }
    }
}

// ---------------------------------------------------------------------------
// tf32 flash attention v3: 128-row q-tile, 4 warps, warp owns 32 rows (mi=2).
// Each K/V B-fragment is reused by 2 mma -> crossbar wavefronts/mma 3.0 -> 2.0.
// Q persists in smem (re-read per kk); grid.x = ceil(T/128), tail masked.
// ---------------------------------------------------------------------------
#define KSTR 68
#define VSTR 72
#define QSTR 68
#define PSTR 68

__global__ __launch_bounds__(128) void attn_tf32(
    const float* __restrict__ q, const float* __restrict__ k,
    const float* __restrict__ v, float* __restrict__ qk_out,
    float* __restrict__ wv_out)
{
    extern __shared__ float sm[];
    float* Qs = sm;                   // [128][68]
    float* Ks = Qs + 128 * QSTR;      // [64][68]
    float* Vs = Ks + 64 * KSTR;       // [64][72]
    float* Ps = Vs + 64 * VSTR;       // [128][68]

    const int tid  = threadIdx.x;
    const int warp = tid >> 5, lane = tid & 31;
    const int g  = lane >> 2, tg = lane & 3;
    const int bh = blockIdx.y;
    const int b  = bh >> 4, h = bh & 15;
    const int t0 = blockIdx.x * 128;
    const int rw = warp * 32;         // warp's first row within tile

    // ---- load Q tile [128][64] -> tf32 smem (clamp rows past T) ----
#pragma unroll
    for (int i = 0; i < 16; i++) {
        int idx = tid + i * 128;          // 0..2047 float4s
        int r = idx >> 4, c = (idx & 15) << 2;
        int gr = min(t0 + r, TT - 1);
        float4 val = *(const float4*)(q + (size_t)(b * TT + gr) * DD + h * DH + c);
        *(float4*)(Qs + r * QSTR + c) = cvt4(val);
    }

    float o[2][8][4];
#pragma unroll
    for (int mi = 0; mi < 2; mi++)
#pragma unroll
        for (int nj = 0; nj < 8; nj++)
#pragma unroll
            for (int r = 0; r < 4; r++) o[mi][nj][r] = 0.f;

    float ms[2][2], ls[2][2];
#pragma unroll
    for (int mi = 0; mi < 2; mi++)
        for (int h2 = 0; h2 < 2; h2++) { ms[mi][h2] = -INFINITY; ls[mi][h2] = 0.f; }

    __syncthreads();

    for (int s0 = 0; s0 < SS; s0 += 64) {
        const int sc = min(64, SS - s0);

        // ---- load K,V chunk [64][64] -> tf32 smem (zero-fill past S) ----
#pragma unroll
        for (int i = 0; i < 8; i++) {
            int idx = tid + i * 128;
            int r = idx >> 4, c = (idx & 15) << 2;
            float4 kv = make_float4(0,0,0,0), vv = kv;
            if (s0 + r < SS) {
                size_t base = (size_t)(b * SS + s0 + r) * DD + h * DH + c;
                kv = *(const float4*)(k + base);
                vv = *(const float4*)(v + base);
            }
            *(float4*)(Ks + r * KSTR + c) = cvt4(kv);
            *(float4*)(Vs + r * VSTR + c) = cvt4(vv);
        }
        __syncthreads();

        // ---- QK^T: 32 rows x 64 s-cols per warp (2 A-frags per B-frag) ----
        float qa[2][8][4];
#pragma unroll
        for (int mi = 0; mi < 2; mi++)
#pragma unroll
            for (int nj = 0; nj < 8; nj++)
#pragma unroll
                for (int r = 0; r < 4; r++) qa[mi][nj][r] = 0.f;

#pragma unroll
        for (int kk = 0; kk < 8; kk++) {
            uint32_t af[2][4], bfr[8][2];
#pragma unroll
            for (int mi = 0; mi < 2; mi++) {
                int row = rw + mi * 16 + g;
                af[mi][0] = __float_as_uint(Qs[row * QSTR + kk * 8 + tg]);
                af[mi][1] = __float_as_uint(Qs[(row + 8) * QSTR + kk * 8 + tg]);
                af[mi][2] = __float_as_uint(Qs[row * QSTR + kk * 8 + tg + 4]);
                af[mi][3] = __float_as_uint(Qs[(row + 8) * QSTR + kk * 8 + tg + 4]);
            }
#pragma unroll
            for (int nj = 0; nj < 8; nj++) {
                int scol = nj * 8 + g;
                bfr[nj][0] = __float_as_uint(Ks[scol * KSTR + kk * 8 + tg]);
                bfr[nj][1] = __float_as_uint(Ks[scol * KSTR + kk * 8 + tg + 4]);
            }
#pragma unroll
            for (int mi = 0; mi < 2; mi++)
#pragma unroll
                for (int nj = 0; nj < 8; nj++)
                    mma8(qa[mi][nj], af[mi], bfr[nj]);
        }

        // ---- write raw logits (mask cols past S, rows past T) ----
#pragma unroll
        for (int mi = 0; mi < 2; mi++) {
            int gr0 = t0 + rw + mi * 16 + g;
            size_t rowbase = ((size_t)bh * TT + gr0) * SS + s0;
#pragma unroll
            for (int nj = 0; nj < 8; nj++) {
                int col = nj * 8 + tg * 2;
                if (col < sc) {
                    if (gr0 < TT)
                        *(float2*)(qk_out + rowbase + col) = make_float2(qa[mi][nj][0], qa[mi][nj][1]);
                    if (gr0 + 8 < TT)
                        *(float2*)(qk_out + rowbase + 8 * SS + col) = make_float2(qa[mi][nj][2], qa[mi][nj][3]);
                } else {
                    qa[mi][nj][0] = qa[mi][nj][1] = -1e30f;
                    qa[mi][nj][2] = qa[mi][nj][3] = -1e30f;
                }
            }
        }

        // ---- warp-local online softmax (4 row-states per thread) ----
#pragma unroll
        for (int mi = 0; mi < 2; mi++) {
            float mx0 = -INFINITY, mx1 = -INFINITY;
#pragma unroll
            for (int nj = 0; nj < 8; nj++) {
                mx0 = fmaxf(mx0, fmaxf(qa[mi][nj][0], qa[mi][nj][1]));
                mx1 = fmaxf(mx1, fmaxf(qa[mi][nj][2], qa[mi][nj][3]));
            }
            mx0 = fmaxf(mx0, __shfl_xor_sync(0xffffffffu, mx0, 1));
            mx0 = fmaxf(mx0, __shfl_xor_sync(0xffffffffu, mx0, 2));
            mx1 = fmaxf(mx1, __shfl_xor_sync(0xffffffffu, mx1, 1));
            mx1 = fmaxf(mx1, __shfl_xor_sync(0xffffffffu, mx1, 2));

            float mn0 = fmaxf(ms[mi][0], mx0), mn1 = fmaxf(ms[mi][1], mx1);
            float c0 = __expf(ms[mi][0] - mn0), c1 = __expf(ms[mi][1] - mn1);
            ms[mi][0] = mn0; ms[mi][1] = mn1;

            float s0r = 0.f, s1r = 0.f;
#pragma unroll
            for (int nj = 0; nj < 8; nj++) {
                float p0 = __expf(qa[mi][nj][0] - mn0);
                float p1 = __expf(qa[mi][nj][1] - mn0);
                float p2 = __expf(qa[mi][nj][2] - mn1);
                float p3 = __expf(qa[mi][nj][3] - mn1);
                s0r += p0 + p1; s1r += p2 + p3;
                qa[mi][nj][0] = __uint_as_float(f2tf32(p0));
                qa[mi][nj][1] = __uint_as_float(f2tf32(p1));
                qa[mi][nj][2] = __uint_as_float(f2tf32(p2));
                qa[mi][nj][3] = __uint_as_float(f2tf32(p3));
            }
            s0r += __shfl_xor_sync(0xffffffffu, s0r, 1);
            s0r += __shfl_xor_sync(0xffffffffu, s0r, 2);
            s1r += __shfl_xor_sync(0xffffffffu, s1r, 1);
            s1r += __shfl_xor_sync(0xffffffffu, s1r, 2);
            ls[mi][0] = ls[mi][0] * c0 + s0r;
            ls[mi][1] = ls[mi][1] * c1 + s1r;

            // rescale O
#pragma unroll
            for (int nj = 0; nj < 8; nj++) {
                o[mi][nj][0] *= c0; o[mi][nj][1] *= c0;
                o[mi][nj][2] *= c1; o[mi][nj][3] *= c1;
            }
        }

        // ---- P -> per-warp smem slab (own 32 rows only) ----
#pragma unroll
        for (int mi = 0; mi < 2; mi++) {
            int row = rw + mi * 16 + g;
#pragma unroll
            for (int nj = 0; nj < 8; nj++) {
                int col = nj * 8 + tg * 2;
                *(float2*)(Ps + row * PSTR + col)       = make_float2(qa[mi][nj][0], qa[mi][nj][1]);
                *(float2*)(Ps + (row + 8) * PSTR + col) = make_float2(qa[mi][nj][2], qa[mi][nj][3]);
            }
        }
        __syncwarp();

        // ---- PV: O += P @ V ----
#pragma unroll
        for (int kk = 0; kk < 8; kk++) {
            uint32_t af[2][4], bfr[8][2];
#pragma unroll
            for (int mi = 0; mi < 2; mi++) {
                int row = rw + mi * 16 + g;
                af[mi][0] = __float_as_uint(Ps[row * PSTR + kk * 8 + tg]);
                af[mi][1] = __float_as_uint(Ps[(row + 8) * PSTR + kk * 8 + tg]);
                af[mi][2] = __float_as_uint(Ps[row * PSTR + kk * 8 + tg + 4]);
                af[mi][3] = __float_as_uint(Ps[(row + 8) * PSTR + kk * 8 + tg + 4]);
            }
#pragma unroll
            for (int nj = 0; nj < 8; nj++) {
                int dcol = nj * 8 + g;
                bfr[nj][0] = __float_as_uint(Vs[(kk * 8 + tg) * VSTR + dcol]);
                bfr[nj][1] = __float_as_uint(Vs[(kk * 8 + tg + 4) * VSTR + dcol]);
            }
#pragma unroll
            for (int mi = 0; mi < 2; mi++)
#pragma unroll
                for (int nj = 0; nj < 8; nj++)
                    mma8(o[mi][nj], af[mi], bfr[nj]);
        }
        __syncthreads();   // protect Ks/Vs before next chunk load
    }

    // ---- normalize, write wv (guard rows past T) ----
#pragma unroll
    for (int mi = 0; mi < 2; mi++) {
        int gr0 = t0 + rw + mi * 16 + g;
        float inv0 = 1.f / ls[mi][0], inv1 = 1.f / ls[mi][1];
        size_t obase = (size_t)(b * TT + gr0) * DD + h * DH;
#pragma unroll
        for (int nj = 0; nj < 8; nj++) {
            int col = nj * 8 + tg * 2;
            if (gr0 < TT)
                *(float2*)(wv_out + obase + col) = make_float2(o[mi][nj][0] * inv0, o[mi][nj][1] * inv0);
            if (gr0 + 8 < TT)
                *(float2*)(wv_out + obase + 8 * DD + col) = make_float2(o[mi][nj][2] * inv1, o[mi][nj][3] * inv1);
        }
    }
}

// ---------------------------------------------------------------------------
extern "C" void kernel_launch(void* const* d_in, const int* in_sizes, int n_in,
                              void* d_out, int out_size)
{
    const float* x  = (const float*)d_in[0];
    const float* xa = (const float*)d_in[1];
    const float* Wq = (const float*)d_in[2];
    const float* bq = (const float*)d_in[3];
    const float* Wk = (const float*)d_in[4];
    const float* Wv = (const float*)d_in[5];
    const float* bv = (const float*)d_in[6];
    const float* Wo = (const float*)d_in[7];
    const float* bo = (const float*)d_in[8];

    float* out = (float*)d_out;               // [8,448,1024]
    float* qk  = out + OUT_ELEMS;             // [8,16,448,1500]

    float* q_s  = nullptr; cudaGetSymbolAddress((void**)&q_s,  g_q);
    float* k_s  = nullptr; cudaGetSymbolAddress((void**)&k_s,  g_k);
    float* v_s  = nullptr; cudaGetSymbolAddress((void**)&v_s,  g_v);
    float* wv_s = nullptr; cudaGetSymbolAddress((void**)&wv_s, g_wv);

    const float scale = 0.3535533905932738f;  // 64^-0.25

    dim3 blk(128);
    gemm_tf32<<<dim3(DD/128, (BB*TT + 127)/128), blk>>>(x,  Wq, bq,      q_s, BB*TT, DD, DD, scale);
    gemm_tf32<<<dim3(DD/128, (BB*SS + 127)/128), blk>>>(xa, Wk, nullptr, k_s, BB*SS, DD, DD, scale);
    gemm_tf32<<<dim3(DD/128, (BB*SS + 127)/128), blk>>>(xa, Wv, bv,      v_s, BB*SS, DD, DD, 1.0f);

    static const size_t attn_smem =
        (128 * QSTR + 64 * KSTR + 64 * VSTR + 128 * PSTR) * sizeof(float);  // 105472
    cudaFuncSetAttribute(attn_tf32, cudaFuncAttributeMaxDynamicSharedMemorySize, (int)attn_smem);
    attn_tf32<<<dim3((TT + 127)/128, BB*HH), dim3(128), attn_smem>>>(q_s, k_s, v_s, qk, wv_s);

    gemm_tf32<<<dim3(DD/128, (BB*TT + 127)/128), blk>>>(wv_s, Wo, bo, out, BB*TT, DD, DD, 1.0f);
}

// round 7
// speedup vs baseline: 1.1721x; 1.1721x over previous
#include <cuda_runtime.h>
#include <math.h>
#include <stdint.h>

// Problem constants
#define BB 8
#define TT 448
#define SS 1500
#define DD 1024
#define HH 16
#define DH 64
#define OUT_ELEMS (BB*TT*DD)

// Scratch
__device__ float g_q  [BB*TT*DD];
__device__ float g_k  [BB*SS*DD];
__device__ float g_v  [BB*SS*DD];
__device__ float g_wv [BB*TT*DD];
__device__ float g_xt [BB*TT*DD];
__device__ float g_xat[BB*SS*DD];
__device__ float g_Wqt[DD*DD];
__device__ float g_Wkt[DD*DD];
__device__ float g_Wvt[DD*DD];
__device__ float g_Wot[DD*DD];

// ---------------------------------------------------------------------------
// tf32 helpers
// ---------------------------------------------------------------------------
__device__ __forceinline__ uint32_t f2tf32(float f) {
    uint32_t r;
    asm("cvt.rna.tf32.f32 %0, %1;" : "=r"(r) : "f"(f));
    return r;
}
__device__ __forceinline__ float4 cvt4(float4 v) {
    return make_float4(__uint_as_float(f2tf32(v.x)), __uint_as_float(f2tf32(v.y)),
                       __uint_as_float(f2tf32(v.z)), __uint_as_float(f2tf32(v.w)));
}
__device__ __forceinline__ void mma8(float* c, const uint32_t* a, const uint32_t* b) {
    asm volatile("mma.sync.aligned.m16n8k8.row.col.f32.tf32.tf32.f32 "
        "{%0,%1,%2,%3}, {%4,%5,%6,%7}, {%8,%9}, {%0,%1,%2,%3};"
        : "+f"(c[0]), "+f"(c[1]), "+f"(c[2]), "+f"(c[3])
        : "r"(a[0]), "r"(a[1]), "r"(a[2]), "r"(a[3]), "r"(b[0]), "r"(b[1]));
}
__device__ __forceinline__ void cp16(const float* s, const float* g) {
    uint32_t sa = (uint32_t)__cvta_generic_to_shared((void*)s);
    asm volatile("cp.async.cg.shared.global [%0], [%1], 16;" :: "r"(sa), "l"(g));
}

// ---------------------------------------------------------------------------
// Elementwise tf32 pre-round (inputs are float4-aligned counts)
// ---------------------------------------------------------------------------
__global__ void cvt_tf32_kernel(const float* __restrict__ in, float* __restrict__ out, int n4)
{
    int i = blockIdx.x * blockDim.x + threadIdx.x;
    if (i < n4) ((float4*)out)[i] = cvt4(((const float4*)in)[i]);
}

// ---------------------------------------------------------------------------
// tf32 GEMM v4: cp.async 5-stage pipeline. Inputs pre-rounded to tf32.
// C = (A@B + bias) * alpha, optional tf32 rounding of output.
// 128x128 tile, BK=16, 128 threads (4 warps 2x2), warp tile 64x64.
// ---------------------------------------------------------------------------
#define STAGES 5
#define GASTR 20
#define GBSTR 136
#define A_STG (128*GASTR)
#define B_STG (16*GBSTR)

__global__ __launch_bounds__(128, 2) void gemm_tf32(
    const float* __restrict__ A, const float* __restrict__ Bm,
    const float* __restrict__ bias, float* __restrict__ C,
    int M, int N, int K, float alpha, int round_out)
{
    extern __shared__ float smg[];
    float* As = smg;                    // [STAGES][128*GASTR]
    float* Bs = smg + STAGES * A_STG;   // [STAGES][16*GBSTR]

    const int tid  = threadIdx.x;
    const int warp = tid >> 5, lane = tid & 31;
    const int wm = warp >> 1, wn = warp & 1;
    const int g  = lane >> 2, tg = lane & 3;
    const int m0 = blockIdx.y * 128, n0 = blockIdx.x * 128;

    const int ar0 = tid >> 2, ac0 = (tid & 3) << 2;   // A rows ar0+32i, col ac0
    const int br0 = tid >> 5, bc0 = lane << 2;        // B rows br0+4i, col bc0

    float acc[4][8][4];
#pragma unroll
    for (int mi = 0; mi < 4; mi++)
#pragma unroll
        for (int nj = 0; nj < 8; nj++)
#pragma unroll
            for (int r = 0; r < 4; r++) acc[mi][nj][r] = 0.f;

    const int nt = K >> 4;   // 64

    // issue tile t into stage stg
    auto issue_tile = [&](int t, int stg) {
        const int k0 = t << 4;
        float* as = As + stg * A_STG;
        float* bs = Bs + stg * B_STG;
#pragma unroll
        for (int i = 0; i < 4; i++) {
            int ra = ar0 + i * 32;
            int gr = min(m0 + ra, M - 1);
            cp16(as + ra * GASTR + ac0, A + (size_t)gr * K + k0 + ac0);
            int rb = br0 + i * 4;
            cp16(bs + rb * GBSTR + bc0, Bm + (size_t)(k0 + rb) * N + n0 + bc0);
        }
    };

    // prologue: tiles 0..3 -> stages 0..3 (one commit group per tile)
#pragma unroll
    for (int t = 0; t < STAGES - 1; t++) {
        issue_tile(t, t);
        asm volatile("cp.async.commit_group;");
    }

    for (int t = 0; t < nt; t++) {
        asm volatile("cp.async.wait_group %0;" :: "n"(STAGES - 2));
        __syncthreads();

        const float* as = As + (t % STAGES) * A_STG;
        const float* bs = Bs + (t % STAGES) * B_STG;

#pragma unroll
        for (int kk = 0; kk < 16; kk += 8) {
            uint32_t af[4][4], bf[8][2];
#pragma unroll
            for (int mi = 0; mi < 4; mi++) {
                int row = wm * 64 + mi * 16 + g;
                af[mi][0] = __float_as_uint(as[row * GASTR + kk + tg]);
                af[mi][1] = __float_as_uint(as[(row + 8) * GASTR + kk + tg]);
                af[mi][2] = __float_as_uint(as[row * GASTR + kk + tg + 4]);
                af[mi][3] = __float_as_uint(as[(row + 8) * GASTR + kk + tg + 4]);
            }
#pragma unroll
            for (int nj = 0; nj < 8; nj++) {
                int col = wn * 64 + nj * 8 + g;
                bf[nj][0] = __float_as_uint(bs[(kk + tg) * GBSTR + col]);
                bf[nj][1] = __float_as_uint(bs[(kk + tg + 4) * GBSTR + col]);
            }
#pragma unroll
            for (int mi = 0; mi < 4; mi++)
#pragma unroll
                for (int nj = 0; nj < 8; nj++)
                    mma8(acc[mi][nj], af[mi], bf[nj]);
        }

        if (t + STAGES - 1 < nt)
            issue_tile(t + STAGES - 1, (t + STAGES - 1) % STAGES);
        asm volatile("cp.async.commit_group;");   // always commit (keeps groups aligned)
    }

    // Epilogue
#pragma unroll
    for (int nj = 0; nj < 8; nj++) {
        int col = n0 + wn * 64 + nj * 8 + tg * 2;
        float2 bv = make_float2(0.f, 0.f);
        if (bias) bv = *(const float2*)(bias + col);
#pragma unroll
        for (int mi = 0; mi < 4; mi++) {
            int r0 = m0 + wm * 64 + mi * 16 + g;
            if (r0 < M) {
                float ox = (acc[mi][nj][0] + bv.x) * alpha;
                float oy = (acc[mi][nj][1] + bv.y) * alpha;
                if (round_out) { ox = __uint_as_float(f2tf32(ox)); oy = __uint_as_float(f2tf32(oy)); }
                *(float2*)(C + (size_t)r0 * N + col) = make_float2(ox, oy);
            }
            if (r0 + 8 < M) {
                float ox = (acc[mi][nj][2] + bv.x) * alpha;
                float oy = (acc[mi][nj][3] + bv.y) * alpha;
                if (round_out) { ox = __uint_as_float(f2tf32(ox)); oy = __uint_as_float(f2tf32(oy)); }
                *(float2*)(C + (size_t)(r0 + 8) * N + col) = make_float2(ox, oy);
            }
        }
    }
}

// ---------------------------------------------------------------------------
// tf32 flash attention (R5 layout): 4 warps, warp owns 16 q-rows x 64 s-cols.
// q/k/v arrive pre-rounded to tf32 -> staging is a plain copy.
// ---------------------------------------------------------------------------
#define KSTR 68
#define VSTR 72
#define PQSTR 68

__global__ __launch_bounds__(128) void attn_tf32(
    const float* __restrict__ q, const float* __restrict__ k,
    const float* __restrict__ v, float* __restrict__ qk_out,
    float* __restrict__ wv_out)
{
    extern __shared__ float sm[];
    float* Ks = sm;                  // [64][68]
    float* Vs = Ks + 64 * KSTR;      // [64][72]
    float* Ps = Vs + 64 * VSTR;      // [64][68]  (also Q staging)

    const int tid  = threadIdx.x;
    const int warp = tid >> 5, lane = tid & 31;
    const int g  = lane >> 2, tg = lane & 3;
    const int bh = blockIdx.y;
    const int b  = bh >> 4, h = bh & 15;
    const int t0 = blockIdx.x * 64;
    const int rw = warp * 16;
    const int grow0 = t0 + rw + g;

    // ---- stage Q through smem (already tf32), pull frags ----
#pragma unroll
    for (int i = 0; i < 8; i++) {
        int idx = tid + i * 128;
        int r = idx >> 4, c = (idx & 15) << 2;
        float4 val = *(const float4*)(q + (size_t)(b * TT + t0 + r) * DD + h * DH + c);
        *(float4*)(Ps + r * PQSTR + c) = val;
    }
    __syncthreads();

    uint32_t qf[8][4];
#pragma unroll
    for (int kk = 0; kk < 8; kk++) {
        int c = kk * 8;
        qf[kk][0] = __float_as_uint(Ps[(rw + g) * PQSTR + c + tg]);
        qf[kk][1] = __float_as_uint(Ps[(rw + g + 8) * PQSTR + c + tg]);
        qf[kk][2] = __float_as_uint(Ps[(rw + g) * PQSTR + c + tg + 4]);
        qf[kk][3] = __float_as_uint(Ps[(rw + g + 8) * PQSTR + c + tg + 4]);
    }

    float o[8][4];
#pragma unroll
    for (int nj = 0; nj < 8; nj++)
#pragma unroll
        for (int r = 0; r < 4; r++) o[nj][r] = 0.f;

    float m0s = -INFINITY, m1s = -INFINITY, l0s = 0.f, l1s = 0.f;

    __syncthreads();

    for (int s0 = 0; s0 < SS; s0 += 64) {
        const int sc = min(64, SS - s0);

        // ---- load K,V chunk (already tf32; zero-fill past S) ----
#pragma unroll
        for (int i = 0; i < 8; i++) {
            int idx = tid + i * 128;
            int r = idx >> 4, c = (idx & 15) << 2;
            float4 kv = make_float4(0,0,0,0), vv = kv;
            if (s0 + r < SS) {
                size_t base = (size_t)(b * SS + s0 + r) * DD + h * DH + c;
                kv = *(const float4*)(k + base);
                vv = *(const float4*)(v + base);
            }
            *(float4*)(Ks + r * KSTR + c) = kv;
            *(float4*)(Vs + r * VSTR + c) = vv;
        }
        __syncthreads();

        // ---- QK^T ----
        float qa[8][4];
#pragma unroll
        for (int nj = 0; nj < 8; nj++)
#pragma unroll
            for (int r = 0; r < 4; r++) qa[nj][r] = 0.f;

#pragma unroll
        for (int kk = 0; kk < 8; kk++) {
            uint32_t bfr[8][2];
#pragma unroll
            for (int nj = 0; nj < 8; nj++) {
                int scol = nj * 8 + g;
                bfr[nj][0] = __float_as_uint(Ks[scol * KSTR + kk * 8 + tg]);
                bfr[nj][1] = __float_as_uint(Ks[scol * KSTR + kk * 8 + tg + 4]);
            }
#pragma unroll
            for (int nj = 0; nj < 8; nj++)
                mma8(qa[nj], qf[kk], bfr[nj]);
        }

        // ---- write raw logits; mask out-of-range ----
        {
            size_t rowbase = ((size_t)bh * TT + grow0) * SS + s0;
#pragma unroll
            for (int nj = 0; nj < 8; nj++) {
                int col = nj * 8 + tg * 2;
                if (col < sc) {
                    *(float2*)(qk_out + rowbase + col)          = make_float2(qa[nj][0], qa[nj][1]);
                    *(float2*)(qk_out + rowbase + 8 * SS + col) = make_float2(qa[nj][2], qa[nj][3]);
                } else {
                    qa[nj][0] = qa[nj][1] = -1e30f;
                    qa[nj][2] = qa[nj][3] = -1e30f;
                }
            }
        }

        // ---- warp-local online softmax ----
        float mx0 = -INFINITY, mx1 = -INFINITY;
#pragma unroll
        for (int nj = 0; nj < 8; nj++) {
            mx0 = fmaxf(mx0, fmaxf(qa[nj][0], qa[nj][1]));
            mx1 = fmaxf(mx1, fmaxf(qa[nj][2], qa[nj][3]));
        }
        mx0 = fmaxf(mx0, __shfl_xor_sync(0xffffffffu, mx0, 1));
        mx0 = fmaxf(mx0, __shfl_xor_sync(0xffffffffu, mx0, 2));
        mx1 = fmaxf(mx1, __shfl_xor_sync(0xffffffffu, mx1, 1));
        mx1 = fmaxf(mx1, __shfl_xor_sync(0xffffffffu, mx1, 2));

        float mn0 = fmaxf(m0s, mx0), mn1 = fmaxf(m1s, mx1);
        float c0 = __expf(m0s - mn0), c1 = __expf(m1s - mn1);
        m0s = mn0; m1s = mn1;

        float s0r = 0.f, s1r = 0.f;
#pragma unroll
        for (int nj = 0; nj < 8; nj++) {
            float p0 = __expf(qa[nj][0] - mn0);
            float p1 = __expf(qa[nj][1] - mn0);
            float p2 = __expf(qa[nj][2] - mn1);
            float p3 = __expf(qa[nj][3] - mn1);
            s0r += p0 + p1; s1r += p2 + p3;
            qa[nj][0] = __uint_as_float(f2tf32(p0));
            qa[nj][1] = __uint_as_float(f2tf32(p1));
            qa[nj][2] = __uint_as_float(f2tf32(p2));
            qa[nj][3] = __uint_as_float(f2tf32(p3));
        }
        s0r += __shfl_xor_sync(0xffffffffu, s0r, 1);
        s0r += __shfl_xor_sync(0xffffffffu, s0r, 2);
        s1r += __shfl_xor_sync(0xffffffffu, s1r, 1);
        s1r += __shfl_xor_sync(0xffffffffu, s1r, 2);
        l0s = l0s * c0 + s0r;
        l1s = l1s * c1 + s1r;

#pragma unroll
        for (int nj = 0; nj < 8; nj++) {
            o[nj][0] *= c0; o[nj][1] *= c0;
            o[nj][2] *= c1; o[nj][3] *= c1;
        }

        // ---- P -> per-warp smem slab ----
#pragma unroll
        for (int nj = 0; nj < 8; nj++) {
            int col = nj * 8 + tg * 2;
            *(float2*)(Ps + (rw + g) * PQSTR + col)     = make_float2(qa[nj][0], qa[nj][1]);
            *(float2*)(Ps + (rw + g + 8) * PQSTR + col) = make_float2(qa[nj][2], qa[nj][3]);
        }
        __syncwarp();

        // ---- PV ----
#pragma unroll
        for (int kk = 0; kk < 8; kk++) {
            uint32_t af[4], bfr[8][2];
            af[0] = __float_as_uint(Ps[(rw + g) * PQSTR + kk * 8 + tg]);
            af[1] = __float_as_uint(Ps[(rw + g + 8) * PQSTR + kk * 8 + tg]);
            af[2] = __float_as_uint(Ps[(rw + g) * PQSTR + kk * 8 + tg + 4]);
            af[3] = __float_as_uint(Ps[(rw + g + 8) * PQSTR + kk * 8 + tg + 4]);
#pragma unroll
            for (int nj = 0; nj < 8; nj++) {
                int dcol = nj * 8 + g;
                bfr[nj][0] = __float_as_uint(Vs[(kk * 8 + tg) * VSTR + dcol]);
                bfr[nj][1] = __float_as_uint(Vs[(kk * 8 + tg + 4) * VSTR + dcol]);
            }
#pragma unroll
            for (int nj = 0; nj < 8; nj++)
                mma8(o[nj], af, bfr[nj]);
        }
        __syncthreads();
    }

    // ---- normalize, write wv (tf32-rounded: consumed by out-GEMM) ----
    float inv0 = 1.f / l0s, inv1 = 1.f / l1s;
    size_t obase = (size_t)(b * TT + grow0) * DD + h * DH;
#pragma unroll
    for (int nj = 0; nj < 8; nj++) {
        int col = nj * 8 + tg * 2;
        float2 r0 = make_float2(__uint_as_float(f2tf32(o[nj][0] * inv0)),
                                __uint_as_float(f2tf32(o[nj][1] * inv0)));
        float2 r1 = make_float2(__uint_as_float(f2tf32(o[nj][2] * inv1)),
                                __uint_as_float(f2tf32(o[nj][3] * inv1)));
        *(float2*)(wv_out + obase + col)          = r0;
        *(float2*)(wv_out + obase + 8 * DD + col) = r1;
    }
}

// ---------------------------------------------------------------------------
extern "C" void kernel_launch(void* const* d_in, const int* in_sizes, int n_in,
                              void* d_out, int out_size)
{
    const float* x  = (const float*)d_in[0];
    const float* xa = (const float*)d_in[1];
    const float* Wq = (const float*)d_in[2];
    const float* bq = (const float*)d_in[3];
    const float* Wk = (const float*)d_in[4];
    const float* Wv = (const float*)d_in[5];
    const float* bv = (const float*)d_in[6];
    const float* Wo = (const float*)d_in[7];
    const float* bo = (const float*)d_in[8];

    float* out = (float*)d_out;               // [8,448,1024]
    float* qk  = out + OUT_ELEMS;             // [8,16,448,1500]

    float *q_s, *k_s, *v_s, *wv_s, *xt, *xat, *Wqt, *Wkt, *Wvt, *Wot;
    cudaGetSymbolAddress((void**)&q_s,  g_q);
    cudaGetSymbolAddress((void**)&k_s,  g_k);
    cudaGetSymbolAddress((void**)&v_s,  g_v);
    cudaGetSymbolAddress((void**)&wv_s, g_wv);
    cudaGetSymbolAddress((void**)&xt,   g_xt);
    cudaGetSymbolAddress((void**)&xat,  g_xat);
    cudaGetSymbolAddress((void**)&Wqt,  g_Wqt);
    cudaGetSymbolAddress((void**)&Wkt,  g_Wkt);
    cudaGetSymbolAddress((void**)&Wvt,  g_Wvt);
    cudaGetSymbolAddress((void**)&Wot,  g_Wot);

    const float scale = 0.3535533905932738f;  // 64^-0.25

    // ---- pre-round all GEMM operands to tf32 ----
    {
        const int thr = 256;
        int n4;
        n4 = BB*TT*DD/4; cvt_tf32_kernel<<<(n4+thr-1)/thr, thr>>>(x,  xt,  n4);
        n4 = BB*SS*DD/4; cvt_tf32_kernel<<<(n4+thr-1)/thr, thr>>>(xa, xat, n4);
        n4 = DD*DD/4;
        cvt_tf32_kernel<<<(n4+thr-1)/thr, thr>>>(Wq, Wqt, n4);
        cvt_tf32_kernel<<<(n4+thr-1)/thr, thr>>>(Wk, Wkt, n4);
        cvt_tf32_kernel<<<(n4+thr-1)/thr, thr>>>(Wv, Wvt, n4);
        cvt_tf32_kernel<<<(n4+thr-1)/thr, thr>>>(Wo, Wot, n4);
    }

    static const size_t gemm_smem = (size_t)(STAGES * (A_STG + B_STG)) * sizeof(float); // 94720
    cudaFuncSetAttribute(gemm_tf32, cudaFuncAttributeMaxDynamicSharedMemorySize, (int)gemm_smem);

    dim3 blk(128);
    gemm_tf32<<<dim3(DD/128, (BB*TT + 127)/128), blk, gemm_smem>>>(xt,  Wqt, bq,      q_s, BB*TT, DD, DD, scale, 1);
    gemm_tf32<<<dim3(DD/128, (BB*SS + 127)/128), blk, gemm_smem>>>(xat, Wkt, nullptr, k_s, BB*SS, DD, DD, scale, 1);
    gemm_tf32<<<dim3(DD/128, (BB*SS + 127)/128), blk, gemm_smem>>>(xat, Wvt, bv,      v_s, BB*SS, DD, DD, 1.0f, 1);

    static const size_t attn_smem = (64 * KSTR + 64 * VSTR + 64 * PQSTR) * sizeof(float);  // 53248
    cudaFuncSetAttribute(attn_tf32, cudaFuncAttributeMaxDynamicSharedMemorySize, (int)attn_smem);
    attn_tf32<<<dim3(TT/64, BB*HH), dim3(128), attn_smem>>>(q_s, k_s, v_s, qk, wv_s);

    gemm_tf32<<<dim3(DD/128, (BB*TT + 127)/128), blk, gemm_smem>>>(wv_s, Wot, bo, out, BB*TT, DD, DD, 1.0f, 0);
}